// round 1
// baseline (speedup 1.0000x reference)
#include <cuda_runtime.h>
#include <cstdint>

#define T2 2048
#define T1 2048
#define EE 512
#define FF 2048
#define NL 4
#define NH 8

// ---------------- scratch (device globals; allocation-free) ----------------
__device__ float g_h   [T2*EE];
__device__ float g_q   [T2*EE];
__device__ float g_k   [T2*EE];
__device__ float g_v   [T2*EE];
__device__ float g_att [T2*EE];
__device__ float g_proj[T2*EE];
__device__ float g_ffn [T2*FF];
__device__ float g_Ks  [T1*EE];
__device__ float g_Vs  [T1*EE];

// ---------------- elementwise copy ----------------
__global__ void copyk(const float* __restrict__ in, float* __restrict__ out) {
    size_t i = ((size_t)blockIdx.x * blockDim.x + threadIdx.x) * 4;
    *(float4*)(out + i) = *(const float4*)(in + i);
}

// ---------------- fused GEMM: C = act(A[M,K] @ B[K,N] + bias[N]) ----------------
// 64x64 block tile, BK=16, 256 threads, 4x4 per thread. All dims multiples of 64/16.
template<int ACT>
__global__ __launch_bounds__(256) void gemm_bias(
    const float* __restrict__ A, const float* __restrict__ B,
    const float* __restrict__ bias, float* __restrict__ C,
    int M, int N, int K)
{
    __shared__ float As[16][68];   // transposed A tile [k][m], padded
    __shared__ float Bs[16][64];   // B tile [k][n]
    const int tid = threadIdx.x;
    const int tx = tid & 15, ty = tid >> 4;
    const int bm = blockIdx.y * 64, bn = blockIdx.x * 64;

    float acc[4][4] = {};

    for (int k0 = 0; k0 < K; k0 += 16) {
        const int ia  = tid * 4;
        const int am_ = ia >> 4, ak = ia & 15;
        float4 a4 = *(const float4*)(A + (size_t)(bm + am_) * K + k0 + ak);
        As[ak + 0][am_] = a4.x; As[ak + 1][am_] = a4.y;
        As[ak + 2][am_] = a4.z; As[ak + 3][am_] = a4.w;
        const int bk = ia >> 6, bn_ = ia & 63;
        *(float4*)&Bs[bk][bn_] = *(const float4*)(B + (size_t)(k0 + bk) * N + bn + bn_);
        __syncthreads();

        #pragma unroll
        for (int kk = 0; kk < 16; kk++) {
            float4 a = *(float4*)&As[kk][ty * 4];
            float4 b = *(float4*)&Bs[kk][tx * 4];
            float av[4] = {a.x, a.y, a.z, a.w};
            float bv[4] = {b.x, b.y, b.z, b.w};
            #pragma unroll
            for (int i = 0; i < 4; i++)
                #pragma unroll
                for (int j = 0; j < 4; j++)
                    acc[i][j] = fmaf(av[i], bv[j], acc[i][j]);
        }
        __syncthreads();
    }

    #pragma unroll
    for (int i = 0; i < 4; i++) {
        float4 w;
        float* wp = &w.x;
        #pragma unroll
        for (int j = 0; j < 4; j++) {
            float c = acc[i][j] + bias[bn + tx * 4 + j];
            if (ACT) c = fmaxf(c, 0.f);
            wp[j] = c;
        }
        *(float4*)(C + (size_t)(bm + ty * 4 + i) * N + bn + tx * 4) = w;
    }
}

// ---------------- flash attention (fp32, per-head, d=64) ----------------
// O[q, hc+d] = softmax_k( Q[q,hc+:] . K[k,hc+:] + mask ) @ V[k,hc+:]
// No 1/sqrt(d) scale (matches reference). maskFull=1: mask[Tq,Tk]; else mask[Tk] vector.
__global__ __launch_bounds__(256) void attn_flash(
    const float* __restrict__ Q, const float* __restrict__ K,
    const float* __restrict__ V, const float* __restrict__ mask,
    float* __restrict__ O, int Tq, int Tk, int maskFull)
{
    extern __shared__ float sm[];
    float (*QsT)[68] = (float(*)[68])(sm);
    float (*KsT)[68] = (float(*)[68])(sm + 64 * 68);
    float (*Vs)[68]  = (float(*)[68])(sm + 2 * 64 * 68);
    float (*Ps)[68]  = (float(*)[68])(sm + 3 * 64 * 68);

    const int tid = threadIdx.x;
    const int tx = tid & 15, ty = tid >> 4;
    const int q0 = blockIdx.x * 64;
    const int hc = blockIdx.y * 64;     // head column offset
    const int dd = (tid & 15) * 4;      // d-coordinate for tile loads
    const int rr = tid >> 4;            // row for tile loads

    // Q tile, transposed: QsT[d][q]
    #pragma unroll
    for (int qr = rr; qr < 64; qr += 16) {
        float4 qv = *(const float4*)(Q + (size_t)(q0 + qr) * EE + hc + dd);
        QsT[dd + 0][qr] = qv.x; QsT[dd + 1][qr] = qv.y;
        QsT[dd + 2][qr] = qv.z; QsT[dd + 3][qr] = qv.w;
    }

    float m_run[4], l_run[4], o[4][4];
    #pragma unroll
    for (int i = 0; i < 4; i++) {
        m_run[i] = -1e30f; l_run[i] = 0.f;
        #pragma unroll
        for (int j = 0; j < 4; j++) o[i][j] = 0.f;
    }

    for (int k0 = 0; k0 < Tk; k0 += 64) {
        __syncthreads();   // protect Ks/Vs/Ps from previous iteration's readers
        #pragma unroll
        for (int kr = rr; kr < 64; kr += 16) {
            float4 kv = *(const float4*)(K + (size_t)(k0 + kr) * EE + hc + dd);
            KsT[dd + 0][kr] = kv.x; KsT[dd + 1][kr] = kv.y;
            KsT[dd + 2][kr] = kv.z; KsT[dd + 3][kr] = kv.w;
            *(float4*)&Vs[kr][dd] = *(const float4*)(V + (size_t)(k0 + kr) * EE + hc + dd);
        }
        __syncthreads();

        // S = Q @ K^T  (4x4 per thread over d=64)
        float s[4][4] = {};
        #pragma unroll 8
        for (int kk = 0; kk < 64; kk++) {
            float4 a = *(float4*)&QsT[kk][ty * 4];
            float4 b = *(float4*)&KsT[kk][tx * 4];
            float av[4] = {a.x, a.y, a.z, a.w};
            float bv[4] = {b.x, b.y, b.z, b.w};
            #pragma unroll
            for (int i = 0; i < 4; i++)
                #pragma unroll
                for (int j = 0; j < 4; j++)
                    s[i][j] = fmaf(av[i], bv[j], s[i][j]);
        }

        // + mask
        if (maskFull) {
            #pragma unroll
            for (int i = 0; i < 4; i++) {
                float4 mv = *(const float4*)(mask + (size_t)(q0 + ty * 4 + i) * Tk + k0 + tx * 4);
                s[i][0] += mv.x; s[i][1] += mv.y; s[i][2] += mv.z; s[i][3] += mv.w;
            }
        } else {
            float4 mv = *(const float4*)(mask + k0 + tx * 4);
            #pragma unroll
            for (int i = 0; i < 4; i++) {
                s[i][0] += mv.x; s[i][1] += mv.y; s[i][2] += mv.z; s[i][3] += mv.w;
            }
        }

        // online softmax (rows shared by 16 lanes with same ty; xor<=8 stays in group)
        #pragma unroll
        for (int i = 0; i < 4; i++) {
            float tm = fmaxf(fmaxf(s[i][0], s[i][1]), fmaxf(s[i][2], s[i][3]));
            tm = fmaxf(tm, __shfl_xor_sync(0xffffffffu, tm, 1));
            tm = fmaxf(tm, __shfl_xor_sync(0xffffffffu, tm, 2));
            tm = fmaxf(tm, __shfl_xor_sync(0xffffffffu, tm, 4));
            tm = fmaxf(tm, __shfl_xor_sync(0xffffffffu, tm, 8));
            float nm = fmaxf(m_run[i], tm);
            float rs = 0.f;
            #pragma unroll
            for (int j = 0; j < 4; j++) {
                float p = __expf(s[i][j] - nm);
                s[i][j] = p; rs += p;
            }
            rs += __shfl_xor_sync(0xffffffffu, rs, 1);
            rs += __shfl_xor_sync(0xffffffffu, rs, 2);
            rs += __shfl_xor_sync(0xffffffffu, rs, 4);
            rs += __shfl_xor_sync(0xffffffffu, rs, 8);
            float sc = __expf(m_run[i] - nm);
            l_run[i] = l_run[i] * sc + rs;
            m_run[i] = nm;
            #pragma unroll
            for (int j = 0; j < 4; j++) o[i][j] *= sc;
            *(float4*)&Ps[ty * 4 + i][tx * 4] = make_float4(s[i][0], s[i][1], s[i][2], s[i][3]);
        }
        __syncthreads();

        // O += P @ V
        #pragma unroll 8
        for (int kk = 0; kk < 64; kk++) {
            float4 b = *(float4*)&Vs[kk][tx * 4];
            float bv[4] = {b.x, b.y, b.z, b.w};
            #pragma unroll
            for (int i = 0; i < 4; i++) {
                float a = Ps[ty * 4 + i][kk];
                #pragma unroll
                for (int j = 0; j < 4; j++)
                    o[i][j] = fmaf(a, bv[j], o[i][j]);
            }
        }
    }

    #pragma unroll
    for (int i = 0; i < 4; i++) {
        float inv = 1.f / l_run[i];
        float4 w = make_float4(o[i][0]*inv, o[i][1]*inv, o[i][2]*inv, o[i][3]*inv);
        *(float4*)(O + (size_t)(q0 + ty * 4 + i) * EE + hc + tx * 4) = w;
    }
}

// ---------------- out = LN(relu(h + a)) * g + b, one block per row ----------------
__global__ __launch_bounds__(128) void add_relu_ln(
    const float* __restrict__ h, const float* __restrict__ a,
    const float* __restrict__ g, const float* __restrict__ b,
    float* __restrict__ out)
{
    __shared__ float red[4];
    const int row = blockIdx.x;
    const int tid = threadIdx.x;
    const int c = tid * 4;

    float4 hv = *(const float4*)(h + (size_t)row * EE + c);
    float4 av = *(const float4*)(a + (size_t)row * EE + c);
    float v[4] = { fmaxf(hv.x + av.x, 0.f), fmaxf(hv.y + av.y, 0.f),
                   fmaxf(hv.z + av.z, 0.f), fmaxf(hv.w + av.w, 0.f) };

    float s = v[0] + v[1] + v[2] + v[3];
    #pragma unroll
    for (int m = 16; m; m >>= 1) s += __shfl_xor_sync(0xffffffffu, s, m);
    if ((tid & 31) == 0) red[tid >> 5] = s;
    __syncthreads();
    float mean = (red[0] + red[1] + red[2] + red[3]) * (1.f / EE);
    __syncthreads();

    float d = 0.f;
    #pragma unroll
    for (int j = 0; j < 4; j++) { float t = v[j] - mean; d += t * t; }
    #pragma unroll
    for (int m = 16; m; m >>= 1) d += __shfl_xor_sync(0xffffffffu, d, m);
    if ((tid & 31) == 0) red[tid >> 5] = d;
    __syncthreads();
    float var = (red[0] + red[1] + red[2] + red[3]) * (1.f / EE);
    float rstd = rsqrtf(var + 1e-5f);

    float4 gv = *(const float4*)(g + c);
    float4 bv = *(const float4*)(b + c);
    float4 w = make_float4((v[0] - mean) * rstd * gv.x + bv.x,
                           (v[1] - mean) * rstd * gv.y + bv.y,
                           (v[2] - mean) * rstd * gv.z + bv.z,
                           (v[3] - mean) * rstd * gv.w + bv.w);
    *(float4*)(out + (size_t)row * EE + c) = w;
}

// ---------------- launch ----------------
extern "C" void kernel_launch(void* const* d_in, const int* in_sizes, int n_in,
                              void* d_out, int out_size)
{
    (void)in_sizes; (void)n_in; (void)out_size;
    const float* x      = (const float*)d_in[0];
    const float* enc    = (const float*)d_in[1];
    const float* am     = (const float*)d_in[2];
    const float* em     = (const float*)d_in[3];
    const float* k_w    = (const float*)d_in[4];
    const float* k_b    = (const float*)d_in[5];
    const float* v_w    = (const float*)d_in[6];
    const float* v_b    = (const float*)d_in[7];
    const float* sa_q_w = (const float*)d_in[8];  const float* sa_q_b = (const float*)d_in[9];
    const float* sa_k_w = (const float*)d_in[10]; const float* sa_k_b = (const float*)d_in[11];
    const float* sa_v_w = (const float*)d_in[12]; const float* sa_v_b = (const float*)d_in[13];
    const float* sa_o_w = (const float*)d_in[14]; const float* sa_o_b = (const float*)d_in[15];
    const float* n1_g   = (const float*)d_in[16]; const float* n1_b   = (const float*)d_in[17];
    const float* ca_o_w = (const float*)d_in[18]; const float* ca_o_b = (const float*)d_in[19];
    const float* n2_g   = (const float*)d_in[20]; const float* n2_b   = (const float*)d_in[21];
    const float* f1_w   = (const float*)d_in[22]; const float* f1_b   = (const float*)d_in[23];
    const float* f2_w   = (const float*)d_in[24]; const float* f2_b   = (const float*)d_in[25];
    const float* n3_g   = (const float*)d_in[26]; const float* n3_b   = (const float*)d_in[27];

    float *h, *q, *k, *v, *att, *proj, *ffn, *Ks, *Vs;
    cudaGetSymbolAddress((void**)&h,    g_h);
    cudaGetSymbolAddress((void**)&q,    g_q);
    cudaGetSymbolAddress((void**)&k,    g_k);
    cudaGetSymbolAddress((void**)&v,    g_v);
    cudaGetSymbolAddress((void**)&att,  g_att);
    cudaGetSymbolAddress((void**)&proj, g_proj);
    cudaGetSymbolAddress((void**)&ffn,  g_ffn);
    cudaGetSymbolAddress((void**)&Ks,   g_Ks);
    cudaGetSymbolAddress((void**)&Vs,   g_Vs);

    const int attSmem = 4 * 64 * 68 * (int)sizeof(float);   // 69632 B
    cudaFuncSetAttribute((const void*)attn_flash,
                         cudaFuncAttributeMaxDynamicSharedMemorySize, attSmem);

    const dim3 gP (EE / 64, T2 / 64);   // [2048,512] gemms
    const dim3 gF1(FF / 64, T2 / 64);   // [2048,2048]
    const dim3 gA (T2 / 64, NH);

    copyk<<<T2 * EE / 1024, 256>>>(x, h);
    gemm_bias<0><<<gP, 256>>>(enc, k_w, k_b, Ks, T1, EE, EE);
    gemm_bias<0><<<gP, 256>>>(enc, v_w, v_b, Vs, T1, EE, EE);

    for (int l = 0; l < NL; l++) {
        const size_t wo = (size_t)l * EE * EE, bo = (size_t)l * EE;
        // self-attention
        gemm_bias<0><<<gP, 256>>>(h, sa_q_w + wo, sa_q_b + bo, q, T2, EE, EE);
        gemm_bias<0><<<gP, 256>>>(h, sa_k_w + wo, sa_k_b + bo, k, T2, EE, EE);
        gemm_bias<0><<<gP, 256>>>(h, sa_v_w + wo, sa_v_b + bo, v, T2, EE, EE);
        attn_flash<<<gA, 256, attSmem>>>(q, k, v, am, att, T2, T2, 1);
        gemm_bias<1><<<gP, 256>>>(att, sa_o_w + wo, sa_o_b + bo, proj, T2, EE, EE);
        add_relu_ln<<<T2, 128>>>(h, proj, n1_g + bo, n1_b + bo, h);
        // cross-attention (Q = h, no projection, per reference)
        attn_flash<<<gA, 256, attSmem>>>(h, Ks, Vs, em, att, T2, T1, 0);
        gemm_bias<1><<<gP, 256>>>(att, ca_o_w + wo, ca_o_b + bo, proj, T2, EE, EE);
        add_relu_ln<<<T2, 128>>>(h, proj, n2_g + bo, n2_b + bo, h);
        // FFN
        gemm_bias<1><<<gF1, 256>>>(h, f1_w + (size_t)l * EE * FF, f1_b + (size_t)l * FF, ffn, T2, FF, EE);
        gemm_bias<0><<<gP, 256>>>(ffn, f2_w + (size_t)l * FF * EE, f2_b + bo, proj, T2, EE, FF);
        add_relu_ln<<<T2, 128>>>(h, proj, n3_g + bo, n3_b + bo, h);
    }

    copyk<<<T2 * EE / 1024, 256>>>(h, (float*)d_out);
}

// round 3
// speedup vs baseline: 1.2091x; 1.2091x over previous
#include <cuda_runtime.h>
#include <cstdint>

#define T2 2048
#define T1 2048
#define EE 512
#define FF 2048
#define NL 4
#define NH 8

// ---------------- scratch (device globals; allocation-free) ----------------
__device__ float g_h   [T2*EE];
__device__ float g_q   [T2*EE];
__device__ float g_k   [T2*EE];
__device__ float g_v   [T2*EE];
__device__ float g_att [T2*EE];
__device__ float g_proj[T2*EE];
__device__ float g_ffn [T2*FF];
__device__ float g_Ks  [T1*EE];
__device__ float g_Vs  [T1*EE];

// ---------------- helpers ----------------
__device__ __forceinline__ void cp16(uint32_t dst, const void* src) {
    asm volatile("cp.async.cg.shared.global [%0], [%1], 16;"
                 :: "r"(dst), "l"(src) : "memory");
}
__device__ __forceinline__ void cp_commit() {
    asm volatile("cp.async.commit_group;" ::: "memory");
}
__device__ __forceinline__ void cp_wait1() {
    asm volatile("cp.async.wait_group 1;" ::: "memory");
}
__device__ __forceinline__ void mma8(float* d, const uint32_t* a, const uint32_t* b) {
    asm volatile(
        "mma.sync.aligned.m16n8k8.row.col.f32.tf32.tf32.f32 "
        "{%0,%1,%2,%3}, {%4,%5,%6,%7}, {%8,%9}, {%0,%1,%2,%3};"
        : "+f"(d[0]), "+f"(d[1]), "+f"(d[2]), "+f"(d[3])
        : "r"(a[0]), "r"(a[1]), "r"(a[2]), "r"(a[3]), "r"(b[0]), "r"(b[1]));
}
__device__ __forceinline__ void split_tf32(float x, uint32_t& hi, uint32_t& lo) {
    uint32_t u = __float_as_uint(x) & 0xFFFFE000u;
    hi = u;
    lo = __float_as_uint(x - __uint_as_float(u));
}

// ---------------- elementwise copy ----------------
__global__ void copyk(const float* __restrict__ in, float* __restrict__ out) {
    size_t i = ((size_t)blockIdx.x * blockDim.x + threadIdx.x) * 4;
    *(float4*)(out + i) = *(const float4*)(in + i);
}

// ---------------- mma.sync tf32 GEMM: C = act(A[M,K] @ B[K,N] + bias[N]) ----
// CTA tile 128x64, 8 warps (4x2), warp tile 32x32, BK=32 with 2-stage cp.async.
// 3xTF32: x = hi + lo (hi = fp32 & 0xFFFFE000); D += ah*bh + ah*bl + al*bh.
// smem (floats): A stage [128][36], B stage [32][72]; two stages.
#define GAS (128 * 36)          // A stage floats
#define GBS (32 * 72)           // B stage floats
#define GSTG (GAS + GBS)        // stage floats
#define GSMEM (2 * GSTG * 4)    // bytes = 55296

__global__ __launch_bounds__(256) void gemm_mma(
    const float* __restrict__ A, const float* __restrict__ B,
    const float* __restrict__ bias, float* __restrict__ C,
    int N, int K, int act)
{
    extern __shared__ float sm[];
    const uint32_t smb = (uint32_t)__cvta_generic_to_shared(sm);
    const int tid = threadIdx.x;
    const int wid = tid >> 5, lane = tid & 31;
    const int g = lane >> 2, t = lane & 3;
    const int bm = blockIdx.y * 128, bn = blockIdx.x * 64;
    const int wm = (wid >> 1) * 32, wn = (wid & 1) * 32;

    float acc[2][4][4];
    #pragma unroll
    for (int mi = 0; mi < 2; mi++)
        #pragma unroll
        for (int nj = 0; nj < 4; nj++)
            #pragma unroll
            for (int r = 0; r < 4; r++) acc[mi][nj][r] = 0.f;

    const int NC = K >> 5;

    // prefetch macro: chunk c into stage s
    #define GPREF(c, s) do {                                                     \
        const float* Ag_ = A + (size_t)bm * K + (size_t)(c) * 32;                \
        const uint32_t Asm_ = smb + (uint32_t)(s) * (GSTG * 4);                  \
        _Pragma("unroll")                                                        \
        for (int j_ = 0; j_ < 4; j_++) {                                         \
            int idx_ = tid + j_ * 256;                                           \
            int m_ = idx_ >> 3, kv_ = idx_ & 7;                                  \
            cp16(Asm_ + (uint32_t)(m_ * 36 + kv_ * 4) * 4,                       \
                 Ag_ + (size_t)m_ * K + kv_ * 4);                                \
        }                                                                        \
        const float* Bg_ = B + (size_t)(c) * 32 * N + bn;                        \
        const uint32_t Bsm_ = smb + (uint32_t)(s) * (GSTG * 4) + GAS * 4;        \
        _Pragma("unroll")                                                        \
        for (int j_ = 0; j_ < 2; j_++) {                                         \
            int idx_ = tid + j_ * 256;                                           \
            int k_ = idx_ >> 4, nv_ = idx_ & 15;                                 \
            cp16(Bsm_ + (uint32_t)(k_ * 72 + nv_ * 4) * 4,                       \
                 Bg_ + (size_t)k_ * N + nv_ * 4);                                \
        }                                                                        \
    } while (0)

    GPREF(0, 0); cp_commit();
    GPREF(1, 1); cp_commit();

    for (int c = 0; c < NC; c++) {
        cp_wait1();
        __syncthreads();
        const float* Ab = sm + (c & 1) * GSTG;
        const float* Bb = Ab + GAS;

        #pragma unroll
        for (int ks = 0; ks < 4; ks++) {
            const int kb = ks * 8;
            uint32_t ah[2][4], al[2][4], bh[4][2], bl[4][2];
            #pragma unroll
            for (int mi = 0; mi < 2; mi++) {
                const int r0 = wm + mi * 16 + g;
                split_tf32(Ab[r0 * 36 + kb + t],           ah[mi][0], al[mi][0]);
                split_tf32(Ab[(r0 + 8) * 36 + kb + t],     ah[mi][1], al[mi][1]);
                split_tf32(Ab[r0 * 36 + kb + t + 4],       ah[mi][2], al[mi][2]);
                split_tf32(Ab[(r0 + 8) * 36 + kb + t + 4], ah[mi][3], al[mi][3]);
            }
            #pragma unroll
            for (int nj = 0; nj < 4; nj++) {
                const int cn = wn + nj * 8 + g;
                split_tf32(Bb[(kb + t) * 72 + cn],     bh[nj][0], bl[nj][0]);
                split_tf32(Bb[(kb + t + 4) * 72 + cn], bh[nj][1], bl[nj][1]);
            }
            #pragma unroll
            for (int mi = 0; mi < 2; mi++)
                #pragma unroll
                for (int nj = 0; nj < 4; nj++) {
                    mma8(acc[mi][nj], ah[mi], bl[nj]);
                    mma8(acc[mi][nj], al[mi], bh[nj]);
                    mma8(acc[mi][nj], ah[mi], bh[nj]);
                }
        }
        __syncthreads();
        if (c + 2 < NC) GPREF(c + 2, c & 1);
        cp_commit();
    }

    // epilogue: bias + optional relu, float2 stores
    #pragma unroll
    for (int mi = 0; mi < 2; mi++) {
        #pragma unroll
        for (int nj = 0; nj < 4; nj++) {
            const int row = bm + wm + mi * 16 + g;
            const int col = bn + wn + nj * 8 + t * 2;
            float2 bv = *(const float2*)(bias + col);
            float2 w0, w1;
            w0.x = acc[mi][nj][0] + bv.x; w0.y = acc[mi][nj][1] + bv.y;
            w1.x = acc[mi][nj][2] + bv.x; w1.y = acc[mi][nj][3] + bv.y;
            if (act) {
                w0.x = fmaxf(w0.x, 0.f); w0.y = fmaxf(w0.y, 0.f);
                w1.x = fmaxf(w1.x, 0.f); w1.y = fmaxf(w1.y, 0.f);
            }
            *(float2*)(C + (size_t)row * N + col) = w0;
            *(float2*)(C + (size_t)(row + 8) * N + col) = w1;
        }
    }
    #undef GPREF
}

// ---------------- flash attention (fp32, per-head, d=64) ----------------
__global__ __launch_bounds__(256) void attn_flash(
    const float* __restrict__ Q, const float* __restrict__ K,
    const float* __restrict__ V, const float* __restrict__ mask,
    float* __restrict__ O, int Tq, int Tk, int maskFull)
{
    extern __shared__ float smf[];
    float (*QsT)[68] = (float(*)[68])(smf);
    float (*KsT)[68] = (float(*)[68])(smf + 64 * 68);
    float (*Vs)[68]  = (float(*)[68])(smf + 2 * 64 * 68);
    float (*Ps)[68]  = (float(*)[68])(smf + 3 * 64 * 68);

    const int tid = threadIdx.x;
    const int tx = tid & 15, ty = tid >> 4;
    const int q0 = blockIdx.x * 64;
    const int hc = blockIdx.y * 64;
    const int dd = (tid & 15) * 4;
    const int rr = tid >> 4;

    #pragma unroll
    for (int qr = rr; qr < 64; qr += 16) {
        float4 qv = *(const float4*)(Q + (size_t)(q0 + qr) * EE + hc + dd);
        QsT[dd + 0][qr] = qv.x; QsT[dd + 1][qr] = qv.y;
        QsT[dd + 2][qr] = qv.z; QsT[dd + 3][qr] = qv.w;
    }

    float m_run[4], l_run[4], o[4][4];
    #pragma unroll
    for (int i = 0; i < 4; i++) {
        m_run[i] = -1e30f; l_run[i] = 0.f;
        #pragma unroll
        for (int j = 0; j < 4; j++) o[i][j] = 0.f;
    }

    for (int k0 = 0; k0 < Tk; k0 += 64) {
        __syncthreads();
        #pragma unroll
        for (int kr = rr; kr < 64; kr += 16) {
            float4 kv = *(const float4*)(K + (size_t)(k0 + kr) * EE + hc + dd);
            KsT[dd + 0][kr] = kv.x; KsT[dd + 1][kr] = kv.y;
            KsT[dd + 2][kr] = kv.z; KsT[dd + 3][kr] = kv.w;
            *(float4*)&Vs[kr][dd] = *(const float4*)(V + (size_t)(k0 + kr) * EE + hc + dd);
        }
        __syncthreads();

        float s[4][4] = {};
        #pragma unroll 8
        for (int kk = 0; kk < 64; kk++) {
            float4 a = *(float4*)&QsT[kk][ty * 4];
            float4 b = *(float4*)&KsT[kk][tx * 4];
            float av[4] = {a.x, a.y, a.z, a.w};
            float bv[4] = {b.x, b.y, b.z, b.w};
            #pragma unroll
            for (int i = 0; i < 4; i++)
                #pragma unroll
                for (int j = 0; j < 4; j++)
                    s[i][j] = fmaf(av[i], bv[j], s[i][j]);
        }

        if (maskFull) {
            #pragma unroll
            for (int i = 0; i < 4; i++) {
                float4 mv = *(const float4*)(mask + (size_t)(q0 + ty * 4 + i) * Tk + k0 + tx * 4);
                s[i][0] += mv.x; s[i][1] += mv.y; s[i][2] += mv.z; s[i][3] += mv.w;
            }
        } else {
            float4 mv = *(const float4*)(mask + k0 + tx * 4);
            #pragma unroll
            for (int i = 0; i < 4; i++) {
                s[i][0] += mv.x; s[i][1] += mv.y; s[i][2] += mv.z; s[i][3] += mv.w;
            }
        }

        #pragma unroll
        for (int i = 0; i < 4; i++) {
            float tm = fmaxf(fmaxf(s[i][0], s[i][1]), fmaxf(s[i][2], s[i][3]));
            tm = fmaxf(tm, __shfl_xor_sync(0xffffffffu, tm, 1));
            tm = fmaxf(tm, __shfl_xor_sync(0xffffffffu, tm, 2));
            tm = fmaxf(tm, __shfl_xor_sync(0xffffffffu, tm, 4));
            tm = fmaxf(tm, __shfl_xor_sync(0xffffffffu, tm, 8));
            float nm = fmaxf(m_run[i], tm);
            float rs = 0.f;
            #pragma unroll
            for (int j = 0; j < 4; j++) {
                float p = __expf(s[i][j] - nm);
                s[i][j] = p; rs += p;
            }
            rs += __shfl_xor_sync(0xffffffffu, rs, 1);
            rs += __shfl_xor_sync(0xffffffffu, rs, 2);
            rs += __shfl_xor_sync(0xffffffffu, rs, 4);
            rs += __shfl_xor_sync(0xffffffffu, rs, 8);
            float sc = __expf(m_run[i] - nm);
            l_run[i] = l_run[i] * sc + rs;
            m_run[i] = nm;
            #pragma unroll
            for (int j = 0; j < 4; j++) o[i][j] *= sc;
            *(float4*)&Ps[ty * 4 + i][tx * 4] = make_float4(s[i][0], s[i][1], s[i][2], s[i][3]);
        }
        __syncthreads();

        #pragma unroll 8
        for (int kk = 0; kk < 64; kk++) {
            float4 b = *(float4*)&Vs[kk][tx * 4];
            float bv[4] = {b.x, b.y, b.z, b.w};
            #pragma unroll
            for (int i = 0; i < 4; i++) {
                float a = Ps[ty * 4 + i][kk];
                #pragma unroll
                for (int j = 0; j < 4; j++)
                    o[i][j] = fmaf(a, bv[j], o[i][j]);
            }
        }
    }

    #pragma unroll
    for (int i = 0; i < 4; i++) {
        float inv = 1.f / l_run[i];
        float4 w = make_float4(o[i][0]*inv, o[i][1]*inv, o[i][2]*inv, o[i][3]*inv);
        *(float4*)(O + (size_t)(q0 + ty * 4 + i) * EE + hc + tx * 4) = w;
    }
}

// ---------------- out = LN(relu(h + a)) * g + b ----------------
__global__ __launch_bounds__(128) void add_relu_ln(
    const float* __restrict__ h, const float* __restrict__ a,
    const float* __restrict__ g, const float* __restrict__ b,
    float* __restrict__ out)
{
    __shared__ float red[4];
    const int row = blockIdx.x;
    const int tid = threadIdx.x;
    const int c = tid * 4;

    float4 hv = *(const float4*)(h + (size_t)row * EE + c);
    float4 av = *(const float4*)(a + (size_t)row * EE + c);
    float v[4] = { fmaxf(hv.x + av.x, 0.f), fmaxf(hv.y + av.y, 0.f),
                   fmaxf(hv.z + av.z, 0.f), fmaxf(hv.w + av.w, 0.f) };

    float s = v[0] + v[1] + v[2] + v[3];
    #pragma unroll
    for (int m = 16; m; m >>= 1) s += __shfl_xor_sync(0xffffffffu, s, m);
    if ((tid & 31) == 0) red[tid >> 5] = s;
    __syncthreads();
    float mean = (red[0] + red[1] + red[2] + red[3]) * (1.f / EE);
    __syncthreads();

    float d = 0.f;
    #pragma unroll
    for (int j = 0; j < 4; j++) { float tt = v[j] - mean; d += tt * tt; }
    #pragma unroll
    for (int m = 16; m; m >>= 1) d += __shfl_xor_sync(0xffffffffu, d, m);
    if ((tid & 31) == 0) red[tid >> 5] = d;
    __syncthreads();
    float var = (red[0] + red[1] + red[2] + red[3]) * (1.f / EE);
    float rstd = rsqrtf(var + 1e-5f);

    float4 gv = *(const float4*)(g + c);
    float4 bv = *(const float4*)(b + c);
    float4 w = make_float4((v[0] - mean) * rstd * gv.x + bv.x,
                           (v[1] - mean) * rstd * gv.y + bv.y,
                           (v[2] - mean) * rstd * gv.z + bv.z,
                           (v[3] - mean) * rstd * gv.w + bv.w);
    *(float4*)(out + (size_t)row * EE + c) = w;
}

// ---------------- launch ----------------
extern "C" void kernel_launch(void* const* d_in, const int* in_sizes, int n_in,
                              void* d_out, int out_size)
{
    (void)in_sizes; (void)n_in; (void)out_size;
    const float* x      = (const float*)d_in[0];
    const float* enc    = (const float*)d_in[1];
    const float* am     = (const float*)d_in[2];
    const float* em     = (const float*)d_in[3];
    const float* k_w    = (const float*)d_in[4];
    const float* k_b    = (const float*)d_in[5];
    const float* v_w    = (const float*)d_in[6];
    const float* v_b    = (const float*)d_in[7];
    const float* sa_q_w = (const float*)d_in[8];  const float* sa_q_b = (const float*)d_in[9];
    const float* sa_k_w = (const float*)d_in[10]; const float* sa_k_b = (const float*)d_in[11];
    const float* sa_v_w = (const float*)d_in[12]; const float* sa_v_b = (const float*)d_in[13];
    const float* sa_o_w = (const float*)d_in[14]; const float* sa_o_b = (const float*)d_in[15];
    const float* n1_g   = (const float*)d_in[16]; const float* n1_b   = (const float*)d_in[17];
    const float* ca_o_w = (const float*)d_in[18]; const float* ca_o_b = (const float*)d_in[19];
    const float* n2_g   = (const float*)d_in[20]; const float* n2_b   = (const float*)d_in[21];
    const float* f1_w   = (const float*)d_in[22]; const float* f1_b   = (const float*)d_in[23];
    const float* f2_w   = (const float*)d_in[24]; const float* f2_b   = (const float*)d_in[25];
    const float* n3_g   = (const float*)d_in[26]; const float* n3_b   = (const float*)d_in[27];

    float *h, *q, *k, *v, *att, *proj, *ffn, *Ks, *Vs;
    cudaGetSymbolAddress((void**)&h,    g_h);
    cudaGetSymbolAddress((void**)&q,    g_q);
    cudaGetSymbolAddress((void**)&k,    g_k);
    cudaGetSymbolAddress((void**)&v,    g_v);
    cudaGetSymbolAddress((void**)&att,  g_att);
    cudaGetSymbolAddress((void**)&proj, g_proj);
    cudaGetSymbolAddress((void**)&ffn,  g_ffn);
    cudaGetSymbolAddress((void**)&Ks,   g_Ks);
    cudaGetSymbolAddress((void**)&Vs,   g_Vs);

    const int attSmem = 4 * 64 * 68 * (int)sizeof(float);
    cudaFuncSetAttribute((const void*)attn_flash,
                         cudaFuncAttributeMaxDynamicSharedMemorySize, attSmem);
    cudaFuncSetAttribute((const void*)gemm_mma,
                         cudaFuncAttributeMaxDynamicSharedMemorySize, GSMEM);

    const dim3 g64(EE / 64, T2 / 128);    // (8,16) for N=512 GEMMs
    const dim3 gF (FF / 64, T2 / 128);    // (32,16) for f1
    const dim3 gA (T2 / 64, NH);

    copyk<<<T2 * EE / 1024, 256>>>(x, h);
    gemm_mma<<<g64, 256, GSMEM>>>(enc, k_w, k_b, Ks, EE, EE, 0);
    gemm_mma<<<g64, 256, GSMEM>>>(enc, v_w, v_b, Vs, EE, EE, 0);

    for (int l = 0; l < NL; l++) {
        const size_t wo = (size_t)l * EE * EE, bo = (size_t)l * EE;
        // self-attention
        gemm_mma<<<g64, 256, GSMEM>>>(h, sa_q_w + wo, sa_q_b + bo, q, EE, EE, 0);
        gemm_mma<<<g64, 256, GSMEM>>>(h, sa_k_w + wo, sa_k_b + bo, k, EE, EE, 0);
        gemm_mma<<<g64, 256, GSMEM>>>(h, sa_v_w + wo, sa_v_b + bo, v, EE, EE, 0);
        attn_flash<<<gA, 256, attSmem>>>(q, k, v, am, att, T2, T2, 1);
        gemm_mma<<<g64, 256, GSMEM>>>(att, sa_o_w + wo, sa_o_b + bo, proj, EE, EE, 1);
        add_relu_ln<<<T2, 128>>>(h, proj, n1_g + bo, n1_b + bo, h);
        // cross-attention (Q = h directly, per reference)
        attn_flash<<<gA, 256, attSmem>>>(h, Ks, Vs, em, att, T2, T1, 0);
        gemm_mma<<<g64, 256, GSMEM>>>(att, ca_o_w + wo, ca_o_b + bo, proj, EE, EE, 1);
        add_relu_ln<<<T2, 128>>>(h, proj, n2_g + bo, n2_b + bo, h);
        // FFN
        gemm_mma<<<gF, 256, GSMEM>>>(h, f1_w + (size_t)l * EE * FF, f1_b + (size_t)l * FF, ffn, FF, EE, 1);
        gemm_mma<<<g64, 256, GSMEM>>>(ffn, f2_w + (size_t)l * FF * EE, f2_b + bo, proj, EE, FF, 0);
        add_relu_ln<<<T2, 128>>>(h, proj, n3_g + bo, n3_b + bo, h);
    }

    copyk<<<T2 * EE / 1024, 256>>>(h, (float*)d_out);
}

// round 4
// speedup vs baseline: 2.6931x; 2.2274x over previous
#include <cuda_runtime.h>
#include <cuda_fp16.h>
#include <cstdint>

#define T2 2048
#define T1 2048
#define EE 512
#define FF 2048
#define NL 4
#define NH 8

// ---------------- scratch (device globals; allocation-free) ----------------
__device__ float g_h   [T2*EE];
__device__ float g_q   [T2*EE];
__device__ float g_k   [T2*EE];
__device__ float g_v   [T2*EE];
__device__ float g_att [T2*EE];
__device__ float g_proj[T2*EE];
__device__ float g_ffn [T2*FF];
__device__ float g_Ks  [T1*EE];
__device__ float g_Vs  [T1*EE];

// ---------------- helpers ----------------
__device__ __forceinline__ void hmma(float* d, const uint32_t* a, const uint32_t* b) {
    asm volatile(
        "mma.sync.aligned.m16n8k16.row.col.f32.f16.f16.f32 "
        "{%0,%1,%2,%3}, {%4,%5,%6,%7}, {%8,%9}, {%0,%1,%2,%3};"
        : "+f"(d[0]), "+f"(d[1]), "+f"(d[2]), "+f"(d[3])
        : "r"(a[0]), "r"(a[1]), "r"(a[2]), "r"(a[3]), "r"(b[0]), "r"(b[1]));
}
#define LDSM4(R, PTR) do {                                                     \
    uint32_t a_ = (uint32_t)__cvta_generic_to_shared(PTR);                     \
    asm volatile("ldmatrix.sync.aligned.m8n8.x4.shared.b16 {%0,%1,%2,%3}, [%4];" \
        : "=r"((R)[0]), "=r"((R)[1]), "=r"((R)[2]), "=r"((R)[3]) : "r"(a_));   \
} while (0)
#define LDSM4T(R, PTR) do {                                                    \
    uint32_t a_ = (uint32_t)__cvta_generic_to_shared(PTR);                     \
    asm volatile("ldmatrix.sync.aligned.m8n8.x4.trans.shared.b16 {%0,%1,%2,%3}, [%4];" \
        : "=r"((R)[0]), "=r"((R)[1]), "=r"((R)[2]), "=r"((R)[3]) : "r"(a_));   \
} while (0)

__device__ __forceinline__ uint32_t packh2(float x, float y) {
    __half2 h = __floats2half2_rn(x, y);
    return *reinterpret_cast<uint32_t*>(&h);
}
// 2-term fp16 split: (x,y) -> hi pair + lo pair; x ≈ hi + lo to ~2.4e-7 rel.
__device__ __forceinline__ void split2(float x, float y, uint32_t& hi, uint32_t& lo) {
    float hx = __half2float(__float2half_rn(x));
    float hy = __half2float(__float2half_rn(y));
    hi = packh2(hx, hy);
    lo = packh2(x - hx, y - hy);
}

// ---------------- elementwise copy ----------------
__global__ void copyk(const float* __restrict__ in, float* __restrict__ out) {
    size_t i = ((size_t)blockIdx.x * blockDim.x + threadIdx.x) * 4;
    *(float4*)(out + i) = *(const float4*)(in + i);
}

// ---------------- fp16-split GEMM: C = act(A[M,K] @ B[K,N] + bias[N]) -------
// CTA 128x64, 8 warps (4x2), warp 32x32, BK=32, 2-stage LDG->STS pipeline.
// smem halves/stage: Ah[128][40]@0, Al@5120, Bh[32][72]@10240, Bl@12544.
#define GST 14848                 // halves per stage
#define GSMEM (2 * GST * 2)       // bytes = 59392

__global__ __launch_bounds__(256, 2) void gemm_mma(
    const float* __restrict__ A, const float* __restrict__ B,
    const float* __restrict__ bias, float* __restrict__ C,
    int N, int K, int act)
{
    extern __shared__ __half hsm[];
    const int tid = threadIdx.x;
    const int wid = tid >> 5, lane = tid & 31;
    const int g = lane >> 2, t = lane & 3;
    const int bm = blockIdx.y * 128, bn = blockIdx.x * 64;
    const int wm = (wid >> 1) * 32, wn = (wid & 1) * 32;

    float acc[2][4][4];
    #pragma unroll
    for (int mi = 0; mi < 2; mi++)
        #pragma unroll
        for (int nj = 0; nj < 4; nj++)
            #pragma unroll
            for (int r = 0; r < 4; r++) acc[mi][nj][r] = 0.f;

    const int NC = K >> 5;
    float4 ra[4], rb[2];

    #define GLDG(c) do {                                                        \
        _Pragma("unroll")                                                       \
        for (int j_ = 0; j_ < 4; j_++) {                                        \
            int idx_ = tid + j_ * 256;                                          \
            ra[j_] = *(const float4*)(A + (size_t)(bm + (idx_ >> 3)) * K        \
                                      + (c) * 32 + (idx_ & 7) * 4);             \
        }                                                                       \
        _Pragma("unroll")                                                       \
        for (int j_ = 0; j_ < 2; j_++) {                                        \
            int idx_ = tid + j_ * 256;                                          \
            rb[j_] = *(const float4*)(B + (size_t)((c) * 32 + (idx_ >> 4)) * N  \
                                      + bn + (idx_ & 15) * 4);                  \
        }                                                                       \
    } while (0)

    #define GSTS(s) do {                                                        \
        __half* st_ = hsm + (s) * GST;                                          \
        _Pragma("unroll")                                                       \
        for (int j_ = 0; j_ < 4; j_++) {                                        \
            int idx_ = tid + j_ * 256;                                          \
            int m_ = idx_ >> 3, kq_ = idx_ & 7;                                 \
            uint32_t h01, l01, h23, l23;                                        \
            split2(ra[j_].x, ra[j_].y, h01, l01);                               \
            split2(ra[j_].z, ra[j_].w, h23, l23);                               \
            *(uint2*)(st_ + m_ * 40 + kq_ * 4) = make_uint2(h01, h23);          \
            *(uint2*)(st_ + 5120 + m_ * 40 + kq_ * 4) = make_uint2(l01, l23);   \
        }                                                                       \
        _Pragma("unroll")                                                       \
        for (int j_ = 0; j_ < 2; j_++) {                                        \
            int idx_ = tid + j_ * 256;                                          \
            int k_ = idx_ >> 4, nq_ = idx_ & 15;                                \
            uint32_t h01, l01, h23, l23;                                        \
            split2(rb[j_].x, rb[j_].y, h01, l01);                               \
            split2(rb[j_].z, rb[j_].w, h23, l23);                               \
            *(uint2*)(st_ + 10240 + k_ * 72 + nq_ * 4) = make_uint2(h01, h23);  \
            *(uint2*)(st_ + 12544 + k_ * 72 + nq_ * 4) = make_uint2(l01, l23);  \
        }                                                                       \
    } while (0)

    GLDG(0); GSTS(0);
    if (NC > 1) GLDG(1);
    __syncthreads();

    for (int c = 0; c < NC; c++) {
        if (c + 1 < NC) GSTS((c + 1) & 1);
        if (c + 2 < NC) GLDG(c + 2);

        __half* st = hsm + (c & 1) * GST;
        #pragma unroll
        for (int ks = 0; ks < 2; ks++) {
            const int kb = ks * 16;
            uint32_t Ahf[2][4], Alf[2][4], Bhf[2][4], Blf[2][4];
            const int arow = (lane & 15), acol = kb + (lane >> 4) * 8;
            #pragma unroll
            for (int mi = 0; mi < 2; mi++) {
                __half* ap = st + (wm + mi * 16 + arow) * 40 + acol;
                LDSM4(Ahf[mi], ap);
                LDSM4(Alf[mi], ap + 5120);
            }
            const int krow = kb + ((lane >> 3) & 1) * 8 + (lane & 7);
            #pragma unroll
            for (int nq = 0; nq < 2; nq++) {
                const int ncol = wn + nq * 16 + ((lane >> 4) & 1) * 8;
                __half* bp = st + 10240 + krow * 72 + ncol;
                LDSM4T(Bhf[nq], bp);
                LDSM4T(Blf[nq], bp + 2304);
            }
            #pragma unroll
            for (int mi = 0; mi < 2; mi++)
                #pragma unroll
                for (int nj = 0; nj < 4; nj++) {
                    const uint32_t* bh = &Bhf[nj >> 1][(nj & 1) * 2];
                    const uint32_t* bl = &Blf[nj >> 1][(nj & 1) * 2];
                    hmma(acc[mi][nj], Ahf[mi], bh);
                    hmma(acc[mi][nj], Ahf[mi], bl);
                    hmma(acc[mi][nj], Alf[mi], bh);
                }
        }
        __syncthreads();
    }

    #pragma unroll
    for (int mi = 0; mi < 2; mi++) {
        #pragma unroll
        for (int nj = 0; nj < 4; nj++) {
            const int row = bm + wm + mi * 16 + g;
            const int col = bn + wn + nj * 8 + t * 2;
            float2 bv = *(const float2*)(bias + col);
            float2 w0, w1;
            w0.x = acc[mi][nj][0] + bv.x; w0.y = acc[mi][nj][1] + bv.y;
            w1.x = acc[mi][nj][2] + bv.x; w1.y = acc[mi][nj][3] + bv.y;
            if (act) {
                w0.x = fmaxf(w0.x, 0.f); w0.y = fmaxf(w0.y, 0.f);
                w1.x = fmaxf(w1.x, 0.f); w1.y = fmaxf(w1.y, 0.f);
            }
            *(float2*)(C + (size_t)row * N + col) = w0;
            *(float2*)(C + (size_t)(row + 8) * N + col) = w1;
        }
    }
    #undef GLDG
    #undef GSTS
}

// ---------------- fp16-split flash attention (per-head, d=64) ---------------
// CTA: 128 q-rows x 1 head; 8 warps, each warp 16 q-rows. KV chunks of 64.
// smem halves: Qh[128][72]@0 Ql@9216 Kh[64][72]@18432 Kl@23040 Vh@27648 Vl@32256
#define ASMEM 73728

__global__ __launch_bounds__(256, 1) void attn_mma(
    const float* __restrict__ Q, const float* __restrict__ K,
    const float* __restrict__ V, const float* __restrict__ mask,
    float* __restrict__ O, int Tk, int maskFull)
{
    extern __shared__ __half hsm[];
    __half* Qh = hsm;
    __half* Ql = hsm + 9216;
    __half* Kh = hsm + 18432;
    __half* Kl = hsm + 23040;
    __half* Vh = hsm + 27648;
    __half* Vl = hsm + 32256;

    const int tid = threadIdx.x;
    const int wid = tid >> 5, lane = tid & 31;
    const int g = lane >> 2, t = lane & 3;
    const int q0 = blockIdx.x * 128, hc = blockIdx.y * 64;
    const int wm = wid * 16;

    // Q tile 128x64 -> split fp16
    #pragma unroll
    for (int j = 0; j < 8; j++) {
        int idx = tid + j * 256;
        int r = idx >> 4, dq = idx & 15;
        float4 qv = *(const float4*)(Q + (size_t)(q0 + r) * EE + hc + dq * 4);
        uint32_t h01, l01, h23, l23;
        split2(qv.x, qv.y, h01, l01); split2(qv.z, qv.w, h23, l23);
        *(uint2*)(Qh + r * 72 + dq * 4) = make_uint2(h01, h23);
        *(uint2*)(Ql + r * 72 + dq * 4) = make_uint2(l01, l23);
    }

    // prefetch KV chunk 0
    float4 rk[4], rv[4];
    #pragma unroll
    for (int j = 0; j < 4; j++) {
        int idx = tid + j * 256;
        int kr = idx >> 4, dq = idx & 15;
        rk[j] = *(const float4*)(K + (size_t)kr * EE + hc + dq * 4);
        rv[j] = *(const float4*)(V + (size_t)kr * EE + hc + dq * 4);
    }

    float m_run[2] = {-1e30f, -1e30f}, l_run[2] = {0.f, 0.f};
    float oacc[8][4];
    #pragma unroll
    for (int nj = 0; nj < 8; nj++)
        #pragma unroll
        for (int r = 0; r < 4; r++) oacc[nj][r] = 0.f;

    __syncthreads();

    const int NCH = Tk >> 6;
    for (int c = 0; c < NCH; c++) {
        // STS KV chunk c (split)
        #pragma unroll
        for (int j = 0; j < 4; j++) {
            int idx = tid + j * 256;
            int kr = idx >> 4, dq = idx & 15;
            uint32_t h01, l01, h23, l23;
            split2(rk[j].x, rk[j].y, h01, l01); split2(rk[j].z, rk[j].w, h23, l23);
            *(uint2*)(Kh + kr * 72 + dq * 4) = make_uint2(h01, h23);
            *(uint2*)(Kl + kr * 72 + dq * 4) = make_uint2(l01, l23);
            split2(rv[j].x, rv[j].y, h01, l01); split2(rv[j].z, rv[j].w, h23, l23);
            *(uint2*)(Vh + kr * 72 + dq * 4) = make_uint2(h01, h23);
            *(uint2*)(Vl + kr * 72 + dq * 4) = make_uint2(l01, l23);
        }
        __syncthreads();

        if (c + 1 < NCH) {
            const float* Kn = K + (size_t)(c + 1) * 64 * EE;
            const float* Vn = V + (size_t)(c + 1) * 64 * EE;
            #pragma unroll
            for (int j = 0; j < 4; j++) {
                int idx = tid + j * 256;
                int kr = idx >> 4, dq = idx & 15;
                rk[j] = *(const float4*)(Kn + (size_t)kr * EE + hc + dq * 4);
                rv[j] = *(const float4*)(Vn + (size_t)kr * EE + hc + dq * 4);
            }
        }

        // ---- S = Q @ K^T (64 cols) ----
        float s[8][4];
        #pragma unroll
        for (int nj = 0; nj < 8; nj++)
            #pragma unroll
            for (int r = 0; r < 4; r++) s[nj][r] = 0.f;

        #pragma unroll
        for (int ks = 0; ks < 4; ks++) {
            uint32_t qh[4], ql[4];
            {
                __half* qp = Qh + (wm + (lane & 15)) * 72 + ks * 16 + (lane >> 4) * 8;
                LDSM4(qh, qp);
                LDSM4(ql, qp + 9216);
            }
            const int kvrow = ((lane >> 4) & 1) * 8 + (lane & 7);
            const int dcol = ks * 16 + ((lane >> 3) & 1) * 8;
            #pragma unroll
            for (int nq = 0; nq < 4; nq++) {
                uint32_t kh4[4], kl4[4];
                __half* kp = Kh + (nq * 16 + kvrow) * 72 + dcol;
                LDSM4(kh4, kp);
                LDSM4(kl4, kp + 4608);
                #pragma unroll
                for (int hb = 0; hb < 2; hb++) {
                    float* sd = s[nq * 2 + hb];
                    const uint32_t* bh = kh4 + hb * 2;
                    const uint32_t* bl = kl4 + hb * 2;
                    hmma(sd, qh, bh);
                    hmma(sd, qh, bl);
                    hmma(sd, ql, bh);
                }
            }
        }

        // ---- mask add ----
        const int k0 = c * 64;
        if (maskFull) {
            const int row0 = q0 + wm + g;
            #pragma unroll
            for (int nj = 0; nj < 8; nj++) {
                float2 m0 = *(const float2*)(mask + (size_t)row0 * Tk + k0 + nj * 8 + t * 2);
                float2 m1 = *(const float2*)(mask + (size_t)(row0 + 8) * Tk + k0 + nj * 8 + t * 2);
                s[nj][0] += m0.x; s[nj][1] += m0.y;
                s[nj][2] += m1.x; s[nj][3] += m1.y;
            }
        } else {
            #pragma unroll
            for (int nj = 0; nj < 8; nj++) {
                float2 mv = *(const float2*)(mask + k0 + nj * 8 + t * 2);
                s[nj][0] += mv.x; s[nj][1] += mv.y;
                s[nj][2] += mv.x; s[nj][3] += mv.y;
            }
        }

        // ---- online softmax (rows g and g+8; cols spread over t-group) ----
        #pragma unroll
        for (int r = 0; r < 2; r++) {
            float tm = -1e30f;
            #pragma unroll
            for (int nj = 0; nj < 8; nj++)
                tm = fmaxf(tm, fmaxf(s[nj][r * 2], s[nj][r * 2 + 1]));
            tm = fmaxf(tm, __shfl_xor_sync(0xffffffffu, tm, 1));
            tm = fmaxf(tm, __shfl_xor_sync(0xffffffffu, tm, 2));
            float nm = fmaxf(m_run[r], tm);
            float sc = __expf(m_run[r] - nm);
            float rs = 0.f;
            #pragma unroll
            for (int nj = 0; nj < 8; nj++) {
                float p0 = __expf(s[nj][r * 2] - nm);
                float p1 = __expf(s[nj][r * 2 + 1] - nm);
                s[nj][r * 2] = p0; s[nj][r * 2 + 1] = p1;
                rs += p0 + p1;
            }
            rs += __shfl_xor_sync(0xffffffffu, rs, 1);
            rs += __shfl_xor_sync(0xffffffffu, rs, 2);
            l_run[r] = l_run[r] * sc + rs;
            m_run[r] = nm;
            #pragma unroll
            for (int nj = 0; nj < 8; nj++) {
                oacc[nj][r * 2] *= sc;
                oacc[nj][r * 2 + 1] *= sc;
            }
        }

        // ---- O += P @ V ----
        #pragma unroll
        for (int ks = 0; ks < 4; ks++) {
            uint32_t ph[4], pl[4];
            split2(s[2 * ks][0],     s[2 * ks][1],     ph[0], pl[0]);
            split2(s[2 * ks][2],     s[2 * ks][3],     ph[1], pl[1]);
            split2(s[2 * ks + 1][0], s[2 * ks + 1][1], ph[2], pl[2]);
            split2(s[2 * ks + 1][2], s[2 * ks + 1][3], ph[3], pl[3]);
            const int krow = ks * 16 + ((lane >> 3) & 1) * 8 + (lane & 7);
            const int nc0 = ((lane >> 4) & 1) * 8;
            #pragma unroll
            for (int nq = 0; nq < 4; nq++) {
                uint32_t vh4[4], vl4[4];
                __half* vp = Vh + krow * 72 + nq * 16 + nc0;
                LDSM4T(vh4, vp);
                LDSM4T(vl4, vp + 4608);
                #pragma unroll
                for (int hb = 0; hb < 2; hb++) {
                    float* od = oacc[nq * 2 + hb];
                    const uint32_t* bh = vh4 + hb * 2;
                    const uint32_t* bl = vl4 + hb * 2;
                    hmma(od, ph, bh);
                    hmma(od, ph, bl);
                    hmma(od, pl, bh);
                }
            }
        }
        __syncthreads();
    }

    // epilogue
    const float inv0 = 1.f / l_run[0], inv1 = 1.f / l_run[1];
    const int row = q0 + wm + g;
    #pragma unroll
    for (int nj = 0; nj < 8; nj++) {
        const int col = hc + nj * 8 + t * 2;
        *(float2*)(O + (size_t)row * EE + col) =
            make_float2(oacc[nj][0] * inv0, oacc[nj][1] * inv0);
        *(float2*)(O + (size_t)(row + 8) * EE + col) =
            make_float2(oacc[nj][2] * inv1, oacc[nj][3] * inv1);
    }
}

// ---------------- out = LN(relu(h + a)) * g + b ----------------
__global__ __launch_bounds__(128) void add_relu_ln(
    const float* __restrict__ h, const float* __restrict__ a,
    const float* __restrict__ g, const float* __restrict__ b,
    float* __restrict__ out)
{
    __shared__ float red[4];
    const int row = blockIdx.x;
    const int tid = threadIdx.x;
    const int c = tid * 4;

    float4 hv = *(const float4*)(h + (size_t)row * EE + c);
    float4 av = *(const float4*)(a + (size_t)row * EE + c);
    float v[4] = { fmaxf(hv.x + av.x, 0.f), fmaxf(hv.y + av.y, 0.f),
                   fmaxf(hv.z + av.z, 0.f), fmaxf(hv.w + av.w, 0.f) };

    float s = v[0] + v[1] + v[2] + v[3];
    #pragma unroll
    for (int m = 16; m; m >>= 1) s += __shfl_xor_sync(0xffffffffu, s, m);
    if ((tid & 31) == 0) red[tid >> 5] = s;
    __syncthreads();
    float mean = (red[0] + red[1] + red[2] + red[3]) * (1.f / EE);
    __syncthreads();

    float d = 0.f;
    #pragma unroll
    for (int j = 0; j < 4; j++) { float tt = v[j] - mean; d += tt * tt; }
    #pragma unroll
    for (int m = 16; m; m >>= 1) d += __shfl_xor_sync(0xffffffffu, d, m);
    if ((tid & 31) == 0) red[tid >> 5] = d;
    __syncthreads();
    float var = (red[0] + red[1] + red[2] + red[3]) * (1.f / EE);
    float rstd = rsqrtf(var + 1e-5f);

    float4 gv = *(const float4*)(g + c);
    float4 bv = *(const float4*)(b + c);
    float4 w = make_float4((v[0] - mean) * rstd * gv.x + bv.x,
                           (v[1] - mean) * rstd * gv.y + bv.y,
                           (v[2] - mean) * rstd * gv.z + bv.z,
                           (v[3] - mean) * rstd * gv.w + bv.w);
    *(float4*)(out + (size_t)row * EE + c) = w;
}

// ---------------- launch ----------------
extern "C" void kernel_launch(void* const* d_in, const int* in_sizes, int n_in,
                              void* d_out, int out_size)
{
    (void)in_sizes; (void)n_in; (void)out_size;
    const float* x      = (const float*)d_in[0];
    const float* enc    = (const float*)d_in[1];
    const float* am     = (const float*)d_in[2];
    const float* em     = (const float*)d_in[3];
    const float* k_w    = (const float*)d_in[4];
    const float* k_b    = (const float*)d_in[5];
    const float* v_w    = (const float*)d_in[6];
    const float* v_b    = (const float*)d_in[7];
    const float* sa_q_w = (const float*)d_in[8];  const float* sa_q_b = (const float*)d_in[9];
    const float* sa_k_w = (const float*)d_in[10]; const float* sa_k_b = (const float*)d_in[11];
    const float* sa_v_w = (const float*)d_in[12]; const float* sa_v_b = (const float*)d_in[13];
    const float* sa_o_w = (const float*)d_in[14]; const float* sa_o_b = (const float*)d_in[15];
    const float* n1_g   = (const float*)d_in[16]; const float* n1_b   = (const float*)d_in[17];
    const float* ca_o_w = (const float*)d_in[18]; const float* ca_o_b = (const float*)d_in[19];
    const float* n2_g   = (const float*)d_in[20]; const float* n2_b   = (const float*)d_in[21];
    const float* f1_w   = (const float*)d_in[22]; const float* f1_b   = (const float*)d_in[23];
    const float* f2_w   = (const float*)d_in[24]; const float* f2_b   = (const float*)d_in[25];
    const float* n3_g   = (const float*)d_in[26]; const float* n3_b   = (const float*)d_in[27];

    float *h, *q, *k, *v, *att, *proj, *ffn, *Ks, *Vs;
    cudaGetSymbolAddress((void**)&h,    g_h);
    cudaGetSymbolAddress((void**)&q,    g_q);
    cudaGetSymbolAddress((void**)&k,    g_k);
    cudaGetSymbolAddress((void**)&v,    g_v);
    cudaGetSymbolAddress((void**)&att,  g_att);
    cudaGetSymbolAddress((void**)&proj, g_proj);
    cudaGetSymbolAddress((void**)&ffn,  g_ffn);
    cudaGetSymbolAddress((void**)&Ks,   g_Ks);
    cudaGetSymbolAddress((void**)&Vs,   g_Vs);

    cudaFuncSetAttribute((const void*)attn_mma,
                         cudaFuncAttributeMaxDynamicSharedMemorySize, ASMEM);
    cudaFuncSetAttribute((const void*)gemm_mma,
                         cudaFuncAttributeMaxDynamicSharedMemorySize, GSMEM);

    const dim3 g64(EE / 64, T2 / 128);    // (8,16) for N=512 GEMMs
    const dim3 gF (FF / 64, T2 / 128);    // (32,16) for f1
    const dim3 gA (T2 / 128, NH);         // (16,8) attention

    copyk<<<T2 * EE / 1024, 256>>>(x, h);
    gemm_mma<<<g64, 256, GSMEM>>>(enc, k_w, k_b, Ks, EE, EE, 0);
    gemm_mma<<<g64, 256, GSMEM>>>(enc, v_w, v_b, Vs, EE, EE, 0);

    for (int l = 0; l < NL; l++) {
        const size_t wo = (size_t)l * EE * EE, bo = (size_t)l * EE;
        // self-attention
        gemm_mma<<<g64, 256, GSMEM>>>(h, sa_q_w + wo, sa_q_b + bo, q, EE, EE, 0);
        gemm_mma<<<g64, 256, GSMEM>>>(h, sa_k_w + wo, sa_k_b + bo, k, EE, EE, 0);
        gemm_mma<<<g64, 256, GSMEM>>>(h, sa_v_w + wo, sa_v_b + bo, v, EE, EE, 0);
        attn_mma<<<gA, 256, ASMEM>>>(q, k, v, am, att, T2, 1);
        gemm_mma<<<g64, 256, GSMEM>>>(att, sa_o_w + wo, sa_o_b + bo, proj, EE, EE, 1);
        add_relu_ln<<<T2, 128>>>(h, proj, n1_g + bo, n1_b + bo, h);
        // cross-attention (Q = h directly, per reference)
        attn_mma<<<gA, 256, ASMEM>>>(h, Ks, Vs, em, att, T1, 0);
        gemm_mma<<<g64, 256, GSMEM>>>(att, ca_o_w + wo, ca_o_b + bo, proj, EE, EE, 1);
        add_relu_ln<<<T2, 128>>>(h, proj, n2_g + bo, n2_b + bo, h);
        // FFN
        gemm_mma<<<gF, 256, GSMEM>>>(h, f1_w + (size_t)l * EE * FF, f1_b + (size_t)l * FF, ffn, FF, EE, 1);
        gemm_mma<<<g64, 256, GSMEM>>>(ffn, f2_w + (size_t)l * FF * EE, f2_b + bo, proj, EE, FF, 0);
        add_relu_ln<<<T2, 128>>>(h, proj, n3_g + bo, n3_b + bo, h);
    }

    copyk<<<T2 * EE / 1024, 256>>>(h, (float*)d_out);
}